// round 15
// baseline (speedup 1.0000x reference)
#include <cuda_runtime.h>
#include <cstdint>
#include <cstddef>

#define Ndim 64
#define Cdim 64
#define Tdim 256
#define Vdim 25
#define Rdim 8
#define Odim 64

// ---------------------------------------------------------------------------
// Global scratch (no allocations allowed anywhere)
// ---------------------------------------------------------------------------
__device__ float g_xs[Ndim * Cdim * Vdim];                    // sum over t of x
__device__ float g_m[(size_t)Ndim * Odim * Vdim * 32];        // m[n][o][u][v], v padded to 32

// ---------------------------------------------------------------------------
// K1: xs[n,c,v] = sum_t x[n,c,t,v]
// grid (Cdim, Ndim), 256 threads. Warp lanes = v (25 active), warps stride t.
// ---------------------------------------------------------------------------
__global__ void k1_reduce_t(const float* __restrict__ x) {
    const int n = blockIdx.y, c = blockIdx.x;
    const int v = threadIdx.x & 31;
    const int tr = threadIdx.x >> 5;
    const float* base = x + ((size_t)(n * Cdim + c) * Tdim) * Vdim;
    float acc = 0.f;
    if (v < Vdim) {
#pragma unroll 4
        for (int t = tr; t < Tdim; t += 8)
            acc += base[t * Vdim + v];
    }
    __shared__ float red[8][32];
    red[tr][v] = acc;
    __syncthreads();
    if (tr == 0 && v < Vdim) {
        float s = 0.f;
#pragma unroll
        for (int j = 0; j < 8; ++j) s += red[j][v];
        g_xs[(n * Cdim + c) * Vdim + v] = s;
    }
}

// ---------------------------------------------------------------------------
// K2: per n: x1,x2 -> att=tanh(x1[u]-x2[v]) -> m[o,u,v] = att@w4 + b4 + A
// grid (Ndim), 256 threads. All tiny.
// ---------------------------------------------------------------------------
__global__ void k2_build_m(const float* __restrict__ A,
                           const float* __restrict__ w1, const float* __restrict__ b1,
                           const float* __restrict__ w2, const float* __restrict__ b2,
                           const float* __restrict__ w4, const float* __restrict__ b4) {
    const int n = blockIdx.x;
    const int tid = threadIdx.x;
    __shared__ float xsn[Cdim * Vdim];          // 1600
    __shared__ float x1s[Rdim * Vdim];          // 200
    __shared__ float x2s[Rdim * Vdim];          // 200
    __shared__ float atts[Rdim * Vdim * Vdim];  // 5000
    __shared__ float w4s[Odim * Rdim];          // 512
    __shared__ float As[Vdim * Vdim];           // 625

    for (int i = tid; i < Cdim * Vdim; i += 256) xsn[i] = g_xs[n * Cdim * Vdim + i];
    for (int i = tid; i < Odim * Rdim; i += 256) w4s[i] = w4[i];
    for (int i = tid; i < Vdim * Vdim; i += 256) As[i] = A[i];
    __syncthreads();

    for (int i = tid; i < Rdim * Vdim; i += 256) {
        const int r = i / Vdim, v = i % Vdim;
        float a1 = 0.f, a2 = 0.f;
#pragma unroll 8
        for (int c = 0; c < Cdim; ++c) {
            const float xv = xsn[c * Vdim + v];
            a1 = fmaf(w1[r * Cdim + c], xv, a1);
            a2 = fmaf(w2[r * Cdim + c], xv, a2);
        }
        x1s[i] = a1 * (1.0f / (float)Tdim) + b1[r];
        x2s[i] = a2 * (1.0f / (float)Tdim) + b2[r];
    }
    __syncthreads();

    for (int i = tid; i < Rdim * Vdim * Vdim; i += 256) {
        const int r = i / (Vdim * Vdim);
        const int uv = i % (Vdim * Vdim);
        const int u = uv / Vdim, v = uv % Vdim;
        atts[i] = tanhf(x1s[r * Vdim + u] - x2s[r * Vdim + v]);
    }
    __syncthreads();

    for (int i = tid; i < Odim * Vdim * Vdim; i += 256) {
        const int o = i / (Vdim * Vdim);
        const int uv = i % (Vdim * Vdim);
        const int u = uv / Vdim, v = uv % Vdim;
        float acc = b4[o] + As[uv];
#pragma unroll
        for (int r = 0; r < Rdim; ++r)
            acc = fmaf(w4s[o * Rdim + r], atts[r * Vdim * Vdim + uv], acc);
        g_m[(((size_t)n * Odim + o) * Vdim + u) * 32 + v] = acc;
    }
}

// ---------------------------------------------------------------------------
// f32x2 helpers (Blackwell packed fp32 FMA: 2x FFMA throughput, PTX-only)
// ---------------------------------------------------------------------------
__device__ __forceinline__ unsigned long long pack2(float lo, float hi) {
    unsigned long long r;
    asm("mov.b64 %0, {%1, %2};" : "=l"(r) : "f"(lo), "f"(hi));
    return r;
}
__device__ __forceinline__ float hsum2(unsigned long long p) {
    float lo, hi;
    asm("mov.b64 {%0, %1}, %2;" : "=f"(lo), "=f"(hi) : "l"(p));
    return lo + hi;
}
__device__ __forceinline__ void fma2(unsigned long long& acc,
                                     unsigned long long a, unsigned long long b) {
    asm("fma.rn.f32x2 %0, %1, %2, %0;" : "+l"(acc) : "l"(a), "l"(b));
}

// ---------------------------------------------------------------------------
// K3: main fused kernel.
// grid (Tdim/8, Ndim), 256 threads, 2 blocks/SM.
// Phase 1: thread (t=warp, v=lane) holds x[c,t,v] for all 64 c packed in 32
//          f32x2 regs; loops o, x3[o][t][v] -> smem (b3 folded in).
// Phase 2: warp w owns o in {8w..8w+7}; lane = u; m-row in regs (loaded ONCE
//          per block per (o,u)); 12 FFMA2 per (o,t); coalesced stores.
// ---------------------------------------------------------------------------
__global__ void __launch_bounds__(256, 2)
k3_main(const float* __restrict__ x,
        const float* __restrict__ w3,
        const float* __restrict__ b3,
        float* __restrict__ out) {
    extern __shared__ float smem[];
    const int bt = blockIdx.x;   // t tile (8 t's)
    const int n  = blockIdx.y;
    const int tid = threadIdx.x;
    const int lane = tid & 31;
    const int w = tid >> 5;

    float* w3s = smem;                       // 4096 floats  [o][c]
    float* x3s = smem + Odim * Cdim;         // 16384 floats [o][t_local][32]
    float* b3s = x3s + Odim * 8 * 32;        // 64 floats

    // cooperative copy of w3 (vectorized) and b3
    {
        const float4* w3v = reinterpret_cast<const float4*>(w3);
        float4* w3sv = reinterpret_cast<float4*>(w3s);
        for (int i = tid; i < Odim * Cdim / 4; i += 256) w3sv[i] = w3v[i];
        if (tid < Odim) b3s[tid] = b3[tid];
    }

    // load this thread's x column (all 64 c) into packed registers
    const int t = bt * 8 + w;
    unsigned long long xp[32];
    {
        const float* xbase = x + ((size_t)n * Cdim * Tdim + t) * Vdim + lane;
#pragma unroll
        for (int c2 = 0; c2 < 32; ++c2) {
            float a = 0.f, b = 0.f;
            if (lane < Vdim) {
                a = xbase[(size_t)(2 * c2 + 0) * (Tdim * Vdim)];
                b = xbase[(size_t)(2 * c2 + 1) * (Tdim * Vdim)];
            }
            xp[c2] = pack2(a, b);
        }
    }
    __syncthreads();

    // ---- Phase 1: x3[o][t][v] for all o ----
#pragma unroll 1
    for (int o = 0; o < Odim; ++o) {
        const ulonglong2* wrow = reinterpret_cast<const ulonglong2*>(w3s + o * Cdim);
        unsigned long long acc = 0ull;
#pragma unroll
        for (int q = 0; q < 16; ++q) {
            const ulonglong2 wv = wrow[q];      // LDS.128: {w[4q],w[4q+1]},{w[4q+2],w[4q+3]}
            fma2(acc, xp[2 * q + 0], wv.x);
            fma2(acc, xp[2 * q + 1], wv.y);
        }
        x3s[(o * 8 + w) * 32 + lane] = hsum2(acc) + b3s[o];
    }
    __syncthreads();

    // ---- Phase 2: out[o][t][u] ----
    const int u = lane;
    const int uc = (u < Vdim) ? u : (Vdim - 1);   // clamp for safe loads; stores guarded
#pragma unroll 1
    for (int oi = 0; oi < 8; ++oi) {
        const int o = w * 8 + oi;
        const float* mrow = g_m + (((size_t)n * Odim + o) * Vdim + uc) * 32;
        unsigned long long mp[12];
#pragma unroll
        for (int j = 0; j < 6; ++j) {
            const ulonglong2 mv = *reinterpret_cast<const ulonglong2*>(mrow + 4 * j);
            mp[2 * j + 0] = mv.x;
            mp[2 * j + 1] = mv.y;
        }
        const float m24 = mrow[24];
        float* outp = out + (((size_t)n * Odim + o) * Tdim + bt * 8) * Vdim + u;
#pragma unroll
        for (int tt = 0; tt < 8; ++tt) {
            const float* x3row = x3s + (o * 8 + tt) * 32;
            unsigned long long acc = 0ull;
#pragma unroll
            for (int j = 0; j < 6; ++j) {
                const ulonglong2 xv = *reinterpret_cast<const ulonglong2*>(x3row + 4 * j);
                fma2(acc, xv.x, mp[2 * j + 0]);
                fma2(acc, xv.y, mp[2 * j + 1]);
            }
            const float res = hsum2(acc) + x3row[24] * m24;
            if (u < Vdim) outp[(size_t)tt * Vdim] = res;
        }
    }
}

// ---------------------------------------------------------------------------
// launch
// ---------------------------------------------------------------------------
extern "C" void kernel_launch(void* const* d_in, const int* in_sizes, int n_in,
                              void* d_out, int out_size) {
    const float* x  = (const float*)d_in[0];
    const float* A  = (const float*)d_in[1];
    const float* w1 = (const float*)d_in[2];
    const float* b1 = (const float*)d_in[3];
    const float* w2 = (const float*)d_in[4];
    const float* b2 = (const float*)d_in[5];
    const float* w3 = (const float*)d_in[6];
    const float* b3 = (const float*)d_in[7];
    const float* w4 = (const float*)d_in[8];
    const float* b4 = (const float*)d_in[9];
    float* out = (float*)d_out;

    const int smem_bytes = (Odim * Cdim + Odim * 8 * 32 + Odim) * (int)sizeof(float); // 82176
    cudaFuncSetAttribute(k3_main, cudaFuncAttributeMaxDynamicSharedMemorySize, smem_bytes);

    k1_reduce_t<<<dim3(Cdim, Ndim), 256>>>(x);
    k2_build_m<<<Ndim, 256>>>(A, w1, b1, w2, b2, w4, b4);
    k3_main<<<dim3(Tdim / 8, Ndim), 256, smem_bytes>>>(x, w3, b3, out);
}

// round 16
// speedup vs baseline: 1.0005x; 1.0005x over previous
#include <cuda_runtime.h>
#include <cstdint>
#include <cstddef>

#define Ndim 64
#define Cdim 64
#define Tdim 256
#define Vdim 25
#define Rdim 8
#define Odim 64

// ---------------------------------------------------------------------------
// Global scratch (no allocations allowed anywhere)
// ---------------------------------------------------------------------------
__device__ float g_xs[Ndim * Cdim * Vdim];                    // sum over t of x
__device__ float g_m[(size_t)Ndim * Odim * Vdim * 32];        // m[n][o][u][v], v padded to 32

// ---------------------------------------------------------------------------
// K1: xs[n,c,v] = sum_t x[n,c,t,v]
// grid (Cdim, Ndim), 256 threads. Warp lanes = v (25 active), warps stride t.
// ---------------------------------------------------------------------------
__global__ void k1_reduce_t(const float* __restrict__ x) {
    const int n = blockIdx.y, c = blockIdx.x;
    const int v = threadIdx.x & 31;
    const int tr = threadIdx.x >> 5;
    const float* base = x + ((size_t)(n * Cdim + c) * Tdim) * Vdim;
    float acc = 0.f;
    if (v < Vdim) {
#pragma unroll 4
        for (int t = tr; t < Tdim; t += 8)
            acc += base[t * Vdim + v];
    }
    __shared__ float red[8][32];
    red[tr][v] = acc;
    __syncthreads();
    if (tr == 0 && v < Vdim) {
        float s = 0.f;
#pragma unroll
        for (int j = 0; j < 8; ++j) s += red[j][v];
        g_xs[(n * Cdim + c) * Vdim + v] = s;
    }
}

// ---------------------------------------------------------------------------
// K2: per n: x1,x2 -> att=tanh(x1[u]-x2[v]) -> m[o,u,v] = att@w4 + b4 + A
// grid (Ndim), 256 threads. All tiny.
// ---------------------------------------------------------------------------
__global__ void k2_build_m(const float* __restrict__ A,
                           const float* __restrict__ w1, const float* __restrict__ b1,
                           const float* __restrict__ w2, const float* __restrict__ b2,
                           const float* __restrict__ w4, const float* __restrict__ b4) {
    const int n = blockIdx.x;
    const int tid = threadIdx.x;
    __shared__ float xsn[Cdim * Vdim];          // 1600
    __shared__ float x1s[Rdim * Vdim];          // 200
    __shared__ float x2s[Rdim * Vdim];          // 200
    __shared__ float atts[Rdim * Vdim * Vdim];  // 5000
    __shared__ float w4s[Odim * Rdim];          // 512
    __shared__ float As[Vdim * Vdim];           // 625

    for (int i = tid; i < Cdim * Vdim; i += 256) xsn[i] = g_xs[n * Cdim * Vdim + i];
    for (int i = tid; i < Odim * Rdim; i += 256) w4s[i] = w4[i];
    for (int i = tid; i < Vdim * Vdim; i += 256) As[i] = A[i];
    __syncthreads();

    for (int i = tid; i < Rdim * Vdim; i += 256) {
        const int r = i / Vdim, v = i % Vdim;
        float a1 = 0.f, a2 = 0.f;
#pragma unroll 8
        for (int c = 0; c < Cdim; ++c) {
            const float xv = xsn[c * Vdim + v];
            a1 = fmaf(w1[r * Cdim + c], xv, a1);
            a2 = fmaf(w2[r * Cdim + c], xv, a2);
        }
        x1s[i] = a1 * (1.0f / (float)Tdim) + b1[r];
        x2s[i] = a2 * (1.0f / (float)Tdim) + b2[r];
    }
    __syncthreads();

    for (int i = tid; i < Rdim * Vdim * Vdim; i += 256) {
        const int r = i / (Vdim * Vdim);
        const int uv = i % (Vdim * Vdim);
        const int u = uv / Vdim, v = uv % Vdim;
        atts[i] = tanhf(x1s[r * Vdim + u] - x2s[r * Vdim + v]);
    }
    __syncthreads();

    for (int i = tid; i < Odim * Vdim * Vdim; i += 256) {
        const int o = i / (Vdim * Vdim);
        const int uv = i % (Vdim * Vdim);
        const int u = uv / Vdim, v = uv % Vdim;
        float acc = b4[o] + As[uv];
#pragma unroll
        for (int r = 0; r < Rdim; ++r)
            acc = fmaf(w4s[o * Rdim + r], atts[r * Vdim * Vdim + uv], acc);
        g_m[(((size_t)n * Odim + o) * Vdim + u) * 32 + v] = acc;
    }
}

// ---------------------------------------------------------------------------
// f32x2 helpers (Blackwell packed fp32 FMA: 2x FFMA throughput, PTX-only)
// ---------------------------------------------------------------------------
__device__ __forceinline__ unsigned long long pack2(float lo, float hi) {
    unsigned long long r;
    asm("mov.b64 %0, {%1, %2};" : "=l"(r) : "f"(lo), "f"(hi));
    return r;
}
__device__ __forceinline__ float hsum2(unsigned long long p) {
    float lo, hi;
    asm("mov.b64 {%0, %1}, %2;" : "=f"(lo), "=f"(hi) : "l"(p));
    return lo + hi;
}
__device__ __forceinline__ void fma2(unsigned long long& acc,
                                     unsigned long long a, unsigned long long b) {
    asm("fma.rn.f32x2 %0, %1, %2, %0;" : "+l"(acc) : "l"(a), "l"(b));
}

// ---------------------------------------------------------------------------
// K3: main fused kernel.
// grid (Tdim/8, Ndim), 256 threads, 2 blocks/SM.
// Phase 1: thread (t=warp, v=lane) holds x[c,t,v] for all 64 c packed in 32
//          f32x2 regs; loops o, x3[o][t][v] -> smem (b3 folded in).
// Phase 2: warp w owns o in {8w..8w+7}; lane = u; m-row in regs (loaded ONCE
//          per block per (o,u)); 12 FFMA2 per (o,t); coalesced stores.
// ---------------------------------------------------------------------------
__global__ void __launch_bounds__(256, 2)
k3_main(const float* __restrict__ x,
        const float* __restrict__ w3,
        const float* __restrict__ b3,
        float* __restrict__ out) {
    extern __shared__ float smem[];
    const int bt = blockIdx.x;   // t tile (8 t's)
    const int n  = blockIdx.y;
    const int tid = threadIdx.x;
    const int lane = tid & 31;
    const int w = tid >> 5;

    float* w3s = smem;                       // 4096 floats  [o][c]
    float* x3s = smem + Odim * Cdim;         // 16384 floats [o][t_local][32]
    float* b3s = x3s + Odim * 8 * 32;        // 64 floats

    // cooperative copy of w3 (vectorized) and b3
    {
        const float4* w3v = reinterpret_cast<const float4*>(w3);
        float4* w3sv = reinterpret_cast<float4*>(w3s);
        for (int i = tid; i < Odim * Cdim / 4; i += 256) w3sv[i] = w3v[i];
        if (tid < Odim) b3s[tid] = b3[tid];
    }

    // load this thread's x column (all 64 c) into packed registers
    const int t = bt * 8 + w;
    unsigned long long xp[32];
    {
        const float* xbase = x + ((size_t)n * Cdim * Tdim + t) * Vdim + lane;
#pragma unroll
        for (int c2 = 0; c2 < 32; ++c2) {
            float a = 0.f, b = 0.f;
            if (lane < Vdim) {
                a = xbase[(size_t)(2 * c2 + 0) * (Tdim * Vdim)];
                b = xbase[(size_t)(2 * c2 + 1) * (Tdim * Vdim)];
            }
            xp[c2] = pack2(a, b);
        }
    }
    __syncthreads();

    // ---- Phase 1: x3[o][t][v] for all o ----
#pragma unroll 1
    for (int o = 0; o < Odim; ++o) {
        const ulonglong2* wrow = reinterpret_cast<const ulonglong2*>(w3s + o * Cdim);
        unsigned long long acc = 0ull;
#pragma unroll
        for (int q = 0; q < 16; ++q) {
            const ulonglong2 wv = wrow[q];      // LDS.128: {w[4q],w[4q+1]},{w[4q+2],w[4q+3]}
            fma2(acc, xp[2 * q + 0], wv.x);
            fma2(acc, xp[2 * q + 1], wv.y);
        }
        x3s[(o * 8 + w) * 32 + lane] = hsum2(acc) + b3s[o];
    }
    __syncthreads();

    // ---- Phase 2: out[o][t][u] ----
    const int u = lane;
    const int uc = (u < Vdim) ? u : (Vdim - 1);   // clamp for safe loads; stores guarded
#pragma unroll 1
    for (int oi = 0; oi < 8; ++oi) {
        const int o = w * 8 + oi;
        const float* mrow = g_m + (((size_t)n * Odim + o) * Vdim + uc) * 32;
        unsigned long long mp[12];
#pragma unroll
        for (int j = 0; j < 6; ++j) {
            const ulonglong2 mv = *reinterpret_cast<const ulonglong2*>(mrow + 4 * j);
            mp[2 * j + 0] = mv.x;
            mp[2 * j + 1] = mv.y;
        }
        const float m24 = mrow[24];
        float* outp = out + (((size_t)n * Odim + o) * Tdim + bt * 8) * Vdim + u;
#pragma unroll
        for (int tt = 0; tt < 8; ++tt) {
            const float* x3row = x3s + (o * 8 + tt) * 32;
            unsigned long long acc = 0ull;
#pragma unroll
            for (int j = 0; j < 6; ++j) {
                const ulonglong2 xv = *reinterpret_cast<const ulonglong2*>(x3row + 4 * j);
                fma2(acc, xv.x, mp[2 * j + 0]);
                fma2(acc, xv.y, mp[2 * j + 1]);
            }
            const float res = hsum2(acc) + x3row[24] * m24;
            if (u < Vdim) outp[(size_t)tt * Vdim] = res;
        }
    }
}

// ---------------------------------------------------------------------------
// launch
// ---------------------------------------------------------------------------
extern "C" void kernel_launch(void* const* d_in, const int* in_sizes, int n_in,
                              void* d_out, int out_size) {
    const float* x  = (const float*)d_in[0];
    const float* A  = (const float*)d_in[1];
    const float* w1 = (const float*)d_in[2];
    const float* b1 = (const float*)d_in[3];
    const float* w2 = (const float*)d_in[4];
    const float* b2 = (const float*)d_in[5];
    const float* w3 = (const float*)d_in[6];
    const float* b3 = (const float*)d_in[7];
    const float* w4 = (const float*)d_in[8];
    const float* b4 = (const float*)d_in[9];
    float* out = (float*)d_out;

    const int smem_bytes = (Odim * Cdim + Odim * 8 * 32 + Odim) * (int)sizeof(float); // 82176
    cudaFuncSetAttribute(k3_main, cudaFuncAttributeMaxDynamicSharedMemorySize, smem_bytes);

    k1_reduce_t<<<dim3(Cdim, Ndim), 256>>>(x);
    k2_build_m<<<Ndim, 256>>>(A, w1, b1, w2, b2, w4, b4);
    k3_main<<<dim3(Tdim / 8, Ndim), 256, smem_bytes>>>(x, w3, b3, out);
}

// round 17
// speedup vs baseline: 1.0054x; 1.0049x over previous
#include <cuda_runtime.h>
#include <cstdint>
#include <cstddef>

#define Ndim 64
#define Cdim 64
#define Tdim 256
#define Vdim 25
#define Rdim 8
#define Odim 64

// ---------------------------------------------------------------------------
// Global scratch (no allocations allowed anywhere)
// ---------------------------------------------------------------------------
__device__ float g_xs[Ndim * Cdim * Vdim];                    // sum over t of x
__device__ float g_m[(size_t)Ndim * Odim * Vdim * 32];        // m[n][o][u][v], v padded to 32

// ---------------------------------------------------------------------------
// K1: xs[n,c,v] = sum_t x[n,c,t,v]
// grid (Cdim, Ndim), 256 threads. Warp lanes = v (25 active), warps stride t.
// ---------------------------------------------------------------------------
__global__ void k1_reduce_t(const float* __restrict__ x) {
    const int n = blockIdx.y, c = blockIdx.x;
    const int v = threadIdx.x & 31;
    const int tr = threadIdx.x >> 5;
    const float* base = x + ((size_t)(n * Cdim + c) * Tdim) * Vdim;
    float acc = 0.f;
    if (v < Vdim) {
#pragma unroll 4
        for (int t = tr; t < Tdim; t += 8)
            acc += base[t * Vdim + v];
    }
    __shared__ float red[8][32];
    red[tr][v] = acc;
    __syncthreads();
    if (tr == 0 && v < Vdim) {
        float s = 0.f;
#pragma unroll
        for (int j = 0; j < 8; ++j) s += red[j][v];
        g_xs[(n * Cdim + c) * Vdim + v] = s;
    }
}

// ---------------------------------------------------------------------------
// K2: per n: x1,x2 -> att=tanh(x1[u]-x2[v]) -> m[o,u,v] = att@w4 + b4 + A
// grid (Ndim), 256 threads. All tiny.
// ---------------------------------------------------------------------------
__global__ void k2_build_m(const float* __restrict__ A,
                           const float* __restrict__ w1, const float* __restrict__ b1,
                           const float* __restrict__ w2, const float* __restrict__ b2,
                           const float* __restrict__ w4, const float* __restrict__ b4) {
    const int n = blockIdx.x;
    const int tid = threadIdx.x;
    __shared__ float xsn[Cdim * Vdim];          // 1600
    __shared__ float x1s[Rdim * Vdim];          // 200
    __shared__ float x2s[Rdim * Vdim];          // 200
    __shared__ float atts[Rdim * Vdim * Vdim];  // 5000
    __shared__ float w4s[Odim * Rdim];          // 512
    __shared__ float As[Vdim * Vdim];           // 625

    for (int i = tid; i < Cdim * Vdim; i += 256) xsn[i] = g_xs[n * Cdim * Vdim + i];
    for (int i = tid; i < Odim * Rdim; i += 256) w4s[i] = w4[i];
    for (int i = tid; i < Vdim * Vdim; i += 256) As[i] = A[i];
    __syncthreads();

    for (int i = tid; i < Rdim * Vdim; i += 256) {
        const int r = i / Vdim, v = i % Vdim;
        float a1 = 0.f, a2 = 0.f;
#pragma unroll 8
        for (int c = 0; c < Cdim; ++c) {
            const float xv = xsn[c * Vdim + v];
            a1 = fmaf(w1[r * Cdim + c], xv, a1);
            a2 = fmaf(w2[r * Cdim + c], xv, a2);
        }
        x1s[i] = a1 * (1.0f / (float)Tdim) + b1[r];
        x2s[i] = a2 * (1.0f / (float)Tdim) + b2[r];
    }
    __syncthreads();

    for (int i = tid; i < Rdim * Vdim * Vdim; i += 256) {
        const int r = i / (Vdim * Vdim);
        const int uv = i % (Vdim * Vdim);
        const int u = uv / Vdim, v = uv % Vdim;
        atts[i] = tanhf(x1s[r * Vdim + u] - x2s[r * Vdim + v]);
    }
    __syncthreads();

    for (int i = tid; i < Odim * Vdim * Vdim; i += 256) {
        const int o = i / (Vdim * Vdim);
        const int uv = i % (Vdim * Vdim);
        const int u = uv / Vdim, v = uv % Vdim;
        float acc = b4[o] + As[uv];
#pragma unroll
        for (int r = 0; r < Rdim; ++r)
            acc = fmaf(w4s[o * Rdim + r], atts[r * Vdim * Vdim + uv], acc);
        g_m[(((size_t)n * Odim + o) * Vdim + u) * 32 + v] = acc;
    }
}

// ---------------------------------------------------------------------------
// f32x2 helpers (Blackwell packed fp32 FMA: 2x FFMA throughput, PTX-only)
// ---------------------------------------------------------------------------
__device__ __forceinline__ unsigned long long pack2(float lo, float hi) {
    unsigned long long r;
    asm("mov.b64 %0, {%1, %2};" : "=l"(r) : "f"(lo), "f"(hi));
    return r;
}
__device__ __forceinline__ float hsum2(unsigned long long p) {
    float lo, hi;
    asm("mov.b64 {%0, %1}, %2;" : "=f"(lo), "=f"(hi) : "l"(p));
    return lo + hi;
}
__device__ __forceinline__ void fma2(unsigned long long& acc,
                                     unsigned long long a, unsigned long long b) {
    asm("fma.rn.f32x2 %0, %1, %2, %0;" : "+l"(acc) : "l"(a), "l"(b));
}

// ---------------------------------------------------------------------------
// K3: main fused kernel.
// grid (Tdim/8, Ndim), 256 threads, 2 blocks/SM.
// Phase 1: thread (t=warp, v=lane) holds x[c,t,v] for all 64 c packed in 32
//          f32x2 regs; loops o, x3[o][t][v] -> smem (b3 folded in).
// Phase 2: warp w owns o in {8w..8w+7}; lane = u; m-row in regs (loaded ONCE
//          per block per (o,u)); 12 FFMA2 per (o,t); coalesced stores.
// ---------------------------------------------------------------------------
__global__ void __launch_bounds__(256, 2)
k3_main(const float* __restrict__ x,
        const float* __restrict__ w3,
        const float* __restrict__ b3,
        float* __restrict__ out) {
    extern __shared__ float smem[];
    const int bt = blockIdx.x;   // t tile (8 t's)
    const int n  = blockIdx.y;
    const int tid = threadIdx.x;
    const int lane = tid & 31;
    const int w = tid >> 5;

    float* w3s = smem;                       // 4096 floats  [o][c]
    float* x3s = smem + Odim * Cdim;         // 16384 floats [o][t_local][32]
    float* b3s = x3s + Odim * 8 * 32;        // 64 floats

    // cooperative copy of w3 (vectorized) and b3
    {
        const float4* w3v = reinterpret_cast<const float4*>(w3);
        float4* w3sv = reinterpret_cast<float4*>(w3s);
        for (int i = tid; i < Odim * Cdim / 4; i += 256) w3sv[i] = w3v[i];
        if (tid < Odim) b3s[tid] = b3[tid];
    }

    // load this thread's x column (all 64 c) into packed registers
    const int t = bt * 8 + w;
    unsigned long long xp[32];
    {
        const float* xbase = x + ((size_t)n * Cdim * Tdim + t) * Vdim + lane;
#pragma unroll
        for (int c2 = 0; c2 < 32; ++c2) {
            float a = 0.f, b = 0.f;
            if (lane < Vdim) {
                a = xbase[(size_t)(2 * c2 + 0) * (Tdim * Vdim)];
                b = xbase[(size_t)(2 * c2 + 1) * (Tdim * Vdim)];
            }
            xp[c2] = pack2(a, b);
        }
    }
    __syncthreads();

    // ---- Phase 1: x3[o][t][v] for all o ----
#pragma unroll 1
    for (int o = 0; o < Odim; ++o) {
        const ulonglong2* wrow = reinterpret_cast<const ulonglong2*>(w3s + o * Cdim);
        unsigned long long acc = 0ull;
#pragma unroll
        for (int q = 0; q < 16; ++q) {
            const ulonglong2 wv = wrow[q];      // LDS.128: {w[4q],w[4q+1]},{w[4q+2],w[4q+3]}
            fma2(acc, xp[2 * q + 0], wv.x);
            fma2(acc, xp[2 * q + 1], wv.y);
        }
        x3s[(o * 8 + w) * 32 + lane] = hsum2(acc) + b3s[o];
    }
    __syncthreads();

    // ---- Phase 2: out[o][t][u] ----
    const int u = lane;
    const int uc = (u < Vdim) ? u : (Vdim - 1);   // clamp for safe loads; stores guarded
#pragma unroll 1
    for (int oi = 0; oi < 8; ++oi) {
        const int o = w * 8 + oi;
        const float* mrow = g_m + (((size_t)n * Odim + o) * Vdim + uc) * 32;
        unsigned long long mp[12];
#pragma unroll
        for (int j = 0; j < 6; ++j) {
            const ulonglong2 mv = *reinterpret_cast<const ulonglong2*>(mrow + 4 * j);
            mp[2 * j + 0] = mv.x;
            mp[2 * j + 1] = mv.y;
        }
        const float m24 = mrow[24];
        float* outp = out + (((size_t)n * Odim + o) * Tdim + bt * 8) * Vdim + u;
#pragma unroll
        for (int tt = 0; tt < 8; ++tt) {
            const float* x3row = x3s + (o * 8 + tt) * 32;
            unsigned long long acc = 0ull;
#pragma unroll
            for (int j = 0; j < 6; ++j) {
                const ulonglong2 xv = *reinterpret_cast<const ulonglong2*>(x3row + 4 * j);
                fma2(acc, xv.x, mp[2 * j + 0]);
                fma2(acc, xv.y, mp[2 * j + 1]);
            }
            const float res = hsum2(acc) + x3row[24] * m24;
            if (u < Vdim) outp[(size_t)tt * Vdim] = res;
        }
    }
}

// ---------------------------------------------------------------------------
// launch
// ---------------------------------------------------------------------------
extern "C" void kernel_launch(void* const* d_in, const int* in_sizes, int n_in,
                              void* d_out, int out_size) {
    const float* x  = (const float*)d_in[0];
    const float* A  = (const float*)d_in[1];
    const float* w1 = (const float*)d_in[2];
    const float* b1 = (const float*)d_in[3];
    const float* w2 = (const float*)d_in[4];
    const float* b2 = (const float*)d_in[5];
    const float* w3 = (const float*)d_in[6];
    const float* b3 = (const float*)d_in[7];
    const float* w4 = (const float*)d_in[8];
    const float* b4 = (const float*)d_in[9];
    float* out = (float*)d_out;

    const int smem_bytes = (Odim * Cdim + Odim * 8 * 32 + Odim) * (int)sizeof(float); // 82176
    cudaFuncSetAttribute(k3_main, cudaFuncAttributeMaxDynamicSharedMemorySize, smem_bytes);

    k1_reduce_t<<<dim3(Cdim, Ndim), 256>>>(x);
    k2_build_m<<<Ndim, 256>>>(A, w1, b1, w2, b2, w4, b4);
    k3_main<<<dim3(Tdim / 8, Ndim), 256, smem_bytes>>>(x, w3, b3, out);
}